// round 1
// baseline (speedup 1.0000x reference)
#include <cuda_runtime.h>

#define NNODES 100000
#define NEDGES 1600000
#define FIN 128
#define FHID 128
#define FOUT 64

// ---------------- scratch (static device globals; no allocation) ----------------
__device__ float g_H[(size_t)NNODES * FHID];    // layer-1 transformed features
__device__ float g_AGG[(size_t)NNODES * FHID];  // layer-1 aggregate
__device__ float g_H2[(size_t)NNODES * FOUT];   // layer-2 transformed features
__device__ int   g_cnt[NNODES];                 // in-degree histogram / fill cursor
__device__ int   g_outcnt[NNODES];              // out-degree histogram
__device__ int   g_rowstart[NNODES + 1];        // CSR row offsets (by dst)
__device__ int   g_esrc[NEDGES];                // CSR column indices (src per dst-row)
__device__ float g_nsrc[NNODES];                // rsqrt(max(deg_out,1))
__device__ float g_ndst[NNODES];                // rsqrt(max(deg_in,1))

// ---------------- small helper kernels ----------------
__global__ void zero_kernel(int* cnt, int* outcnt) {
    int i = blockIdx.x * blockDim.x + threadIdx.x;
    if (i < NNODES) { cnt[i] = 0; outcnt[i] = 0; }
}

__global__ void hist_kernel(const int* __restrict__ src, const int* __restrict__ dst,
                            int* cnt, int* outcnt) {
    int e = blockIdx.x * blockDim.x + threadIdx.x;
    if (e < NEDGES) {
        atomicAdd(&cnt[dst[e]], 1);
        atomicAdd(&outcnt[src[e]], 1);
    }
}

// single-block exclusive scan of g_cnt -> g_rowstart; zeroes g_cnt for cursor reuse
__global__ void scan_kernel(int* __restrict__ cnt, int* __restrict__ rowstart) {
    __shared__ int part[1024];
    const int t = threadIdx.x;
    const int chunk = (NNODES + 1023) / 1024;   // 98
    const int lo = t * chunk;
    const int hi = min(lo + chunk, NNODES);
    int s = 0;
    for (int i = lo; i < hi; i++) s += cnt[i];
    part[t] = s;
    __syncthreads();
    // Hillis-Steele inclusive scan
    for (int off = 1; off < 1024; off <<= 1) {
        int v = (t >= off) ? part[t - off] : 0;
        __syncthreads();
        part[t] += v;
        __syncthreads();
    }
    int run = part[t] - s;  // exclusive prefix
    for (int i = lo; i < hi; i++) {
        rowstart[i] = run;
        run += cnt[i];
        cnt[i] = 0;         // reset cursor
    }
    if (t == 1023) rowstart[NNODES] = part[1023];
}

__global__ void norms_kernel(const int* __restrict__ outcnt,
                             const int* __restrict__ rowstart,
                             float* nsrc, float* ndst) {
    int i = blockIdx.x * blockDim.x + threadIdx.x;
    if (i < NNODES) {
        nsrc[i] = rsqrtf(fmaxf((float)outcnt[i], 1.f));
        ndst[i] = rsqrtf(fmaxf((float)(rowstart[i + 1] - rowstart[i]), 1.f));
    }
}

__global__ void fill_kernel(const int* __restrict__ src, const int* __restrict__ dst,
                            const int* __restrict__ rowstart, int* cnt,
                            int* __restrict__ esrc) {
    int e = blockIdx.x * blockDim.x + threadIdx.x;
    if (e < NEDGES) {
        int d = dst[e];
        int pos = rowstart[d] + atomicAdd(&cnt[d], 1);
        esrc[pos] = src[e];
    }
}

// ---------------- fp32 SIMT GEMM (M x 128) @ (128 x BN) ----------------
// MODE 0: a = A[i,k]                     (layer-1: feat)
// MODE 1: a = relu(A[i,k]*ndst[i]+b1[k]) (layer-2: aggregate transform)
// epilogue: C[i,:] = dot * nsrc[i]
template <int BN, int MODE>
__global__ __launch_bounds__(256)
void gemm_kernel(const float* __restrict__ A,
                 const float* __restrict__ B,
                 float* __restrict__ C,
                 const float* __restrict__ nsrc,
                 const float* __restrict__ ndst,
                 const float* __restrict__ bias,
                 int M)
{
    constexpr int BM = 128, BK = 32;
    constexpr int LDA = BM + 4;                 // pad keeps 16B alignment + few conflicts
    constexpr int WN = (BN == 128) ? 64 : 32;   // warp n extent
    constexpr int TN = WN / 8;                  // per-thread n (8 or 4)

    __shared__ float As[BK][LDA];               // transposed: As[k][m]
    __shared__ float Bs[BK][BN];
    __shared__ float bsh[FHID];

    const int tid  = threadIdx.x;
    const int warp = tid >> 5;
    const int lane = tid & 31;
    const int warp_m = warp & 3;                // 4 warps along M (32 rows each)
    const int warp_n = warp >> 2;               // 2 warps along N
    const int lm = lane & 3;                    // 4 lanes along m (8 rows each)
    const int ln = lane >> 2;                   // 8 lanes along n
    const int m0 = warp_m * 32 + lm * 8;
    const int n0 = warp_n * WN + ln * TN;
    const int blockRow = blockIdx.x * BM;

    if (MODE == 1 && tid < FHID) bsh[tid] = bias[tid];

    float acc[8][TN];
#pragma unroll
    for (int i = 0; i < 8; i++)
#pragma unroll
        for (int j = 0; j < TN; j++) acc[i][j] = 0.f;

    const int lr = tid >> 3;    // base row 0..31
    const int c4 = tid & 7;     // k quad

    for (int kc = 0; kc < FIN; kc += BK) {
        __syncthreads();
        // A tile -> transposed smem
#pragma unroll
        for (int it = 0; it < 4; it++) {
            int row  = lr + 32 * it;
            int grow = blockRow + row;
            float4 v = make_float4(0.f, 0.f, 0.f, 0.f);
            if (grow < M) {
                v = *(const float4*)(A + (size_t)grow * FIN + kc + c4 * 4);
                if (MODE == 1) {
                    float nd = ndst[grow];
                    v.x = fmaxf(fmaf(v.x, nd, bsh[kc + c4 * 4 + 0]), 0.f);
                    v.y = fmaxf(fmaf(v.y, nd, bsh[kc + c4 * 4 + 1]), 0.f);
                    v.z = fmaxf(fmaf(v.z, nd, bsh[kc + c4 * 4 + 2]), 0.f);
                    v.w = fmaxf(fmaf(v.w, nd, bsh[kc + c4 * 4 + 3]), 0.f);
                }
            }
            As[c4 * 4 + 0][row] = v.x;
            As[c4 * 4 + 1][row] = v.y;
            As[c4 * 4 + 2][row] = v.z;
            As[c4 * 4 + 3][row] = v.w;
        }
        // B tile
#pragma unroll
        for (int it = 0; it < (BK * BN / 4) / 256; it++) {
            int idx = it * 256 + tid;
            int kb  = idx / (BN / 4);
            int cb  = idx % (BN / 4);
            *(float4*)&Bs[kb][cb * 4] =
                *(const float4*)(B + (size_t)(kc + kb) * BN + cb * 4);
        }
        __syncthreads();

#pragma unroll
        for (int k = 0; k < BK; k++) {
            float a[8];
            *(float4*)&a[0] = *(const float4*)&As[k][m0];
            *(float4*)&a[4] = *(const float4*)&As[k][m0 + 4];
            float b[TN];
            *(float4*)&b[0] = *(const float4*)&Bs[k][n0];
            if (TN == 8)
                *(float4*)&b[4] = *(const float4*)&Bs[k][n0 + 4];
#pragma unroll
            for (int i = 0; i < 8; i++)
#pragma unroll
                for (int j = 0; j < TN; j++)
                    acc[i][j] = fmaf(a[i], b[j], acc[i][j]);
        }
    }

#pragma unroll
    for (int i = 0; i < 8; i++) {
        int grow = blockRow + m0 + i;
        if (grow < M) {
            float s = nsrc[grow];
#pragma unroll
            for (int j = 0; j < TN; j += 4) {
                float4 o;
                o.x = acc[i][j + 0] * s;
                o.y = acc[i][j + 1] * s;
                o.z = acc[i][j + 2] * s;
                o.w = acc[i][j + 3] * s;
                *(float4*)(C + (size_t)grow * BN + n0 + j) = o;
            }
        }
    }
}

// ---------------- gather SpMM: out[i,:] = sum_{e in row i} H[esrc[e],:] ----------------
// EPI: out = acc*ndst[i] + bias  (layer-2 final, writes d_out directly)
template <int C, bool EPI>
__global__ void spmm_kernel(const float* __restrict__ H,
                            const int* __restrict__ rowstart,
                            const int* __restrict__ esrc,
                            float* __restrict__ out,
                            const float* __restrict__ ndst,
                            const float* __restrict__ bias,
                            int n)
{
    constexpr int C4  = C / 4;      // float4 lanes per row
    constexpr int RPW = 32 / C4;    // rows per warp
    int gt = blockIdx.x * blockDim.x + threadIdx.x;
    int w = gt >> 5;
    int lane = gt & 31;
    int sub = lane / C4;
    int lc  = lane % C4;
    int row = w * RPW + sub;
    if (row >= n) return;

    int beg = rowstart[row];
    int end = rowstart[row + 1];
    float4 acc = make_float4(0.f, 0.f, 0.f, 0.f);
    for (int e = beg; e < end; e++) {
        int s = esrc[e];
        float4 v = *((const float4*)(H + (size_t)s * C) + lc);
        acc.x += v.x; acc.y += v.y; acc.z += v.z; acc.w += v.w;
    }
    if (EPI) {
        float nd = ndst[row];
        float4 b = ((const float4*)bias)[lc];
        acc.x = fmaf(acc.x, nd, b.x);
        acc.y = fmaf(acc.y, nd, b.y);
        acc.z = fmaf(acc.z, nd, b.z);
        acc.w = fmaf(acc.w, nd, b.w);
    }
    *((float4*)(out + (size_t)row * C) + lc) = acc;
}

// ---------------- launch ----------------
extern "C" void kernel_launch(void* const* d_in, const int* in_sizes, int n_in,
                              void* d_out, int out_size)
{
    float *H, *AGG, *H2, *nsrc, *ndst;
    int *cnt, *outcnt, *rowstart, *esrc;
    cudaGetSymbolAddress((void**)&H,        g_H);
    cudaGetSymbolAddress((void**)&AGG,      g_AGG);
    cudaGetSymbolAddress((void**)&H2,       g_H2);
    cudaGetSymbolAddress((void**)&cnt,      g_cnt);
    cudaGetSymbolAddress((void**)&outcnt,   g_outcnt);
    cudaGetSymbolAddress((void**)&rowstart, g_rowstart);
    cudaGetSymbolAddress((void**)&esrc,     g_esrc);
    cudaGetSymbolAddress((void**)&nsrc,     g_nsrc);
    cudaGetSymbolAddress((void**)&ndst,     g_ndst);

    const float* W1 = (const float*)d_in[9];
    const float* b1 = (const float*)d_in[10];
    const float* W2 = (const float*)d_in[11];
    const float* b2 = (const float*)d_in[12];

    const int NB_N = (NNODES + 255) / 256;     // 391
    const int NB_E = (NEDGES + 255) / 256;     // 6250
    const int NB_G = (NNODES + 127) / 128;     // 782

    for (int g = 0; g < 3; g++) {
        const float* feat = (const float*)d_in[3 * g + 0];
        const int*   src  = (const int*)  d_in[3 * g + 1];
        const int*   dst  = (const int*)  d_in[3 * g + 2];
        float* out = (float*)d_out + (size_t)g * NNODES * FOUT;

        zero_kernel <<<NB_N, 256>>>(cnt, outcnt);
        hist_kernel <<<NB_E, 256>>>(src, dst, cnt, outcnt);
        scan_kernel <<<1, 1024>>>(cnt, rowstart);
        norms_kernel<<<NB_N, 256>>>(outcnt, rowstart, nsrc, ndst);
        fill_kernel <<<NB_E, 256>>>(src, dst, rowstart, cnt, esrc);

        // layer 1: H = (feat @ W1) * nsrc ; AGG = CSR-gather(H)
        gemm_kernel<128, 0><<<NB_G, 256>>>(feat, W1, H, nsrc, nullptr, nullptr, NNODES);
        spmm_kernel<128, false><<<(NNODES * 32 + 255) / 256, 256>>>(
            H, rowstart, esrc, AGG, nullptr, nullptr, NNODES);

        // layer 2: H2 = (relu(AGG*ndst+b1) @ W2) * nsrc ; out = gather(H2)*ndst + b2
        gemm_kernel<64, 1><<<NB_G, 256>>>(AGG, W2, H2, nsrc, ndst, b1, NNODES);
        spmm_kernel<64, true><<<(NNODES * 16 + 255) / 256, 256>>>(
            H2, rowstart, esrc, out, ndst, b2, NNODES);
    }
}

// round 2
// speedup vs baseline: 1.0298x; 1.0298x over previous
#include <cuda_runtime.h>
#include <cstdint>

#define NNODES 100000
#define NEDGES 1600000
#define FIN 128
#define FHID 128
#define FOUT 64

// ---------------- scratch (static device globals; no allocation) ----------------
__device__ float g_H[(size_t)NNODES * FHID];    // layer-1 transformed features
__device__ float g_AGG[(size_t)NNODES * FHID];  // layer-1 aggregate
__device__ float g_H2[(size_t)NNODES * FOUT];   // layer-2 transformed features
__device__ int   g_cnt[NNODES];                 // in-degree histogram / fill cursor
__device__ int   g_outcnt[NNODES];              // out-degree histogram
__device__ int   g_rowstart[NNODES + 1];        // CSR row offsets (by dst)
__device__ int   g_esrc[NEDGES];                // CSR column indices (src per dst-row)
__device__ float g_nsrc[NNODES];                // rsqrt(max(deg_out,1))
__device__ float g_ndst[NNODES];                // rsqrt(max(deg_in,1))

// ---------------- small helper kernels ----------------
__global__ void zero_kernel(int* cnt, int* outcnt) {
    int i = blockIdx.x * blockDim.x + threadIdx.x;
    if (i < NNODES) { cnt[i] = 0; outcnt[i] = 0; }
}

__global__ void hist_kernel(const int* __restrict__ src, const int* __restrict__ dst,
                            int* cnt, int* outcnt) {
    int e = blockIdx.x * blockDim.x + threadIdx.x;
    if (e < NEDGES) {
        atomicAdd(&cnt[dst[e]], 1);
        atomicAdd(&outcnt[src[e]], 1);
    }
}

// single-block exclusive scan of g_cnt -> g_rowstart; zeroes g_cnt for cursor reuse
__global__ void scan_kernel(int* __restrict__ cnt, int* __restrict__ rowstart) {
    __shared__ int part[1024];
    const int t = threadIdx.x;
    const int chunk = (NNODES + 1023) / 1024;   // 98
    const int lo = t * chunk;
    const int hi = min(lo + chunk, NNODES);
    int s = 0;
    for (int i = lo; i < hi; i++) s += cnt[i];
    part[t] = s;
    __syncthreads();
    for (int off = 1; off < 1024; off <<= 1) {
        int v = (t >= off) ? part[t - off] : 0;
        __syncthreads();
        part[t] += v;
        __syncthreads();
    }
    int run = part[t] - s;  // exclusive prefix
    for (int i = lo; i < hi; i++) {
        rowstart[i] = run;
        run += cnt[i];
        cnt[i] = 0;         // reset cursor
    }
    if (t == 1023) rowstart[NNODES] = part[1023];
}

__global__ void norms_kernel(const int* __restrict__ outcnt,
                             const int* __restrict__ rowstart,
                             float* nsrc, float* ndst) {
    int i = blockIdx.x * blockDim.x + threadIdx.x;
    if (i < NNODES) {
        nsrc[i] = rsqrtf(fmaxf((float)outcnt[i], 1.f));
        ndst[i] = rsqrtf(fmaxf((float)(rowstart[i + 1] - rowstart[i]), 1.f));
    }
}

__global__ void fill_kernel(const int* __restrict__ src, const int* __restrict__ dst,
                            const int* __restrict__ rowstart, int* cnt,
                            int* __restrict__ esrc) {
    int e = blockIdx.x * blockDim.x + threadIdx.x;
    if (e < NEDGES) {
        int d = dst[e];
        int pos = rowstart[d] + atomicAdd(&cnt[d], 1);
        esrc[pos] = src[e];
    }
}

// ---------------- tf32 helpers ----------------
__device__ __forceinline__ float tf32_rna(float x) {
    uint32_t u;
    asm("cvt.rna.tf32.f32 %0, %1;" : "=r"(u) : "f"(x));
    return __uint_as_float(u);
}

__device__ __forceinline__ void mma_tf32(float* d, const float* a, const float* b) {
    asm volatile(
        "mma.sync.aligned.m16n8k8.row.col.f32.tf32.tf32.f32 "
        "{%0,%1,%2,%3},{%4,%5,%6,%7},{%8,%9},{%0,%1,%2,%3};"
        : "+f"(d[0]), "+f"(d[1]), "+f"(d[2]), "+f"(d[3])
        : "r"(__float_as_uint(a[0])), "r"(__float_as_uint(a[1])),
          "r"(__float_as_uint(a[2])), "r"(__float_as_uint(a[3])),
          "r"(__float_as_uint(b[0])), "r"(__float_as_uint(b[1])));
}

// ---------------- tensor-core GEMM (M x 128) @ (128 x BN), 3xTF32 ----------------
// MODE 0: a = A[i,k]                     (layer-1: feat)
// MODE 1: a = relu(A[i,k]*ndst[i]+b1[k]) (layer-2: aggregate transform)
// epilogue: C[i,:] = dot * nsrc[i]
template <int BN, int MODE>
__global__ __launch_bounds__(256)
void gemm_tc(const float* __restrict__ A,
             const float* __restrict__ B,
             float* __restrict__ C,
             const float* __restrict__ nsrc,
             const float* __restrict__ ndst,
             const float* __restrict__ bias,
             int M)
{
    constexpr int BM = 128, BK = 16;
    constexpr int LDA = BK + 4;                  // 20: conflict-free frag loads
    constexpr int LDB = BN + 8;                  // conflict-free frag loads
    constexpr int WN  = (BN == 128) ? 64 : 32;   // warp n extent
    constexpr int NT  = WN / 8;                  // n-tiles per warp (8 or 4)

    __shared__ float Ah[BM][LDA];
    __shared__ float Al[BM][LDA];
    __shared__ float Bh[BK][LDB];
    __shared__ float Bl[BK][LDB];
    __shared__ float bsh[FHID];

    const int tid  = threadIdx.x;
    const int warp = tid >> 5;
    const int lane = tid & 31;
    const int warp_m = warp & 3;          // 4 warps along M (32 rows each)
    const int warp_n = warp >> 2;         // 2 warps along N
    const int m0w = warp_m * 32;
    const int n0w = warp_n * WN;
    const int g  = lane >> 2;             // group id 0..7
    const int tg = lane & 3;              // thread-in-group 0..3
    const int blockRow = blockIdx.x * BM;

    if (MODE == 1 && tid < FHID) bsh[tid] = bias[tid];

    float acc[2][NT][4];
#pragma unroll
    for (int mi = 0; mi < 2; mi++)
#pragma unroll
        for (int ni = 0; ni < NT; ni++)
#pragma unroll
            for (int j = 0; j < 4; j++) acc[mi][ni][j] = 0.f;

    const int arow = tid >> 2;            // 0..63 (A load: 2 passes of 64 rows)
    const int acol = tid & 3;             // float4 column within 16-wide chunk

    for (int kc = 0; kc < FIN; kc += BK) {
        __syncthreads();
        // ---- A tile -> smem (hi/lo split) ----
#pragma unroll
        for (int it = 0; it < 2; it++) {
            int row  = arow + 64 * it;
            int grow = blockRow + row;
            float4 v = make_float4(0.f, 0.f, 0.f, 0.f);
            if (grow < M) {
                v = *(const float4*)(A + (size_t)grow * FIN + kc + acol * 4);
                if (MODE == 1) {
                    float nd = ndst[grow];
                    v.x = fmaxf(fmaf(v.x, nd, bsh[kc + acol * 4 + 0]), 0.f);
                    v.y = fmaxf(fmaf(v.y, nd, bsh[kc + acol * 4 + 1]), 0.f);
                    v.z = fmaxf(fmaf(v.z, nd, bsh[kc + acol * 4 + 2]), 0.f);
                    v.w = fmaxf(fmaf(v.w, nd, bsh[kc + acol * 4 + 3]), 0.f);
                }
            }
            float hx = tf32_rna(v.x), hy = tf32_rna(v.y);
            float hz = tf32_rna(v.z), hw = tf32_rna(v.w);
            Ah[row][acol * 4 + 0] = hx;  Al[row][acol * 4 + 0] = tf32_rna(v.x - hx);
            Ah[row][acol * 4 + 1] = hy;  Al[row][acol * 4 + 1] = tf32_rna(v.y - hy);
            Ah[row][acol * 4 + 2] = hz;  Al[row][acol * 4 + 2] = tf32_rna(v.z - hz);
            Ah[row][acol * 4 + 3] = hw;  Al[row][acol * 4 + 3] = tf32_rna(v.w - hw);
        }
        // ---- B tile -> smem (hi/lo split) ----
        {
            constexpr int F4PT = (BK * BN / 4) / 256;  // float4 per thread (2 or 1)
            int brow = tid >> 4;                        // 0..15
            int bcol = tid & 15;                        // float4 units
#pragma unroll
            for (int it = 0; it < F4PT; it++) {
                int c4 = bcol + it * 16;
                float4 v = *(const float4*)(B + (size_t)(kc + brow) * BN + c4 * 4);
                float hx = tf32_rna(v.x), hy = tf32_rna(v.y);
                float hz = tf32_rna(v.z), hw = tf32_rna(v.w);
                Bh[brow][c4 * 4 + 0] = hx;  Bl[brow][c4 * 4 + 0] = tf32_rna(v.x - hx);
                Bh[brow][c4 * 4 + 1] = hy;  Bl[brow][c4 * 4 + 1] = tf32_rna(v.y - hy);
                Bh[brow][c4 * 4 + 2] = hz;  Bl[brow][c4 * 4 + 2] = tf32_rna(v.z - hz);
                Bh[brow][c4 * 4 + 3] = hw;  Bl[brow][c4 * 4 + 3] = tf32_rna(v.w - hw);
            }
        }
        __syncthreads();

#pragma unroll
        for (int kk = 0; kk < BK; kk += 8) {
            // A fragments (m16n8k8 layout): a0:(g,tg) a1:(g+8,tg) a2:(g,tg+4) a3:(g+8,tg+4)
            float ah[2][4], al[2][4];
#pragma unroll
            for (int mi = 0; mi < 2; mi++) {
                int r = m0w + mi * 16 + g;
                ah[mi][0] = Ah[r][kk + tg];       al[mi][0] = Al[r][kk + tg];
                ah[mi][1] = Ah[r + 8][kk + tg];   al[mi][1] = Al[r + 8][kk + tg];
                ah[mi][2] = Ah[r][kk + tg + 4];   al[mi][2] = Al[r][kk + tg + 4];
                ah[mi][3] = Ah[r + 8][kk + tg + 4]; al[mi][3] = Al[r + 8][kk + tg + 4];
            }
            // B fragments: b0:(k=tg, n=g) b1:(k=tg+4, n=g)
            float bh[NT][2], bl[NT][2];
#pragma unroll
            for (int ni = 0; ni < NT; ni++) {
                int c = n0w + ni * 8 + g;
                bh[ni][0] = Bh[kk + tg][c];       bl[ni][0] = Bl[kk + tg][c];
                bh[ni][1] = Bh[kk + tg + 4][c];   bl[ni][1] = Bl[kk + tg + 4][c];
            }
            // 3xTF32: lo*hi + hi*lo + hi*hi
#pragma unroll
            for (int mi = 0; mi < 2; mi++)
#pragma unroll
                for (int ni = 0; ni < NT; ni++) {
                    mma_tf32(acc[mi][ni], al[mi], bh[ni]);
                    mma_tf32(acc[mi][ni], ah[mi], bl[ni]);
                    mma_tf32(acc[mi][ni], ah[mi], bh[ni]);
                }
        }
    }

    // ---- epilogue: C[i,:] = acc * nsrc[i] ----
    // c0,c1: row=g,  cols 2*tg,2*tg+1 ; c2,c3: row=g+8
#pragma unroll
    for (int mi = 0; mi < 2; mi++) {
        int r0 = blockRow + m0w + mi * 16 + g;
        int r1 = r0 + 8;
        float s0 = (r0 < M) ? nsrc[r0] : 0.f;
        float s1 = (r1 < M) ? nsrc[r1] : 0.f;
#pragma unroll
        for (int ni = 0; ni < NT; ni++) {
            int col = n0w + ni * 8 + 2 * tg;
            if (r0 < M) {
                float2 o = make_float2(acc[mi][ni][0] * s0, acc[mi][ni][1] * s0);
                *(float2*)(C + (size_t)r0 * BN + col) = o;
            }
            if (r1 < M) {
                float2 o = make_float2(acc[mi][ni][2] * s1, acc[mi][ni][3] * s1);
                *(float2*)(C + (size_t)r1 * BN + col) = o;
            }
        }
    }
}

// ---------------- gather SpMM: out[i,:] = sum_{e in row i} H[esrc[e],:] ----------------
template <int C, bool EPI>
__global__ void spmm_kernel(const float* __restrict__ H,
                            const int* __restrict__ rowstart,
                            const int* __restrict__ esrc,
                            float* __restrict__ out,
                            const float* __restrict__ ndst,
                            const float* __restrict__ bias,
                            int n)
{
    constexpr int C4  = C / 4;      // float4 lanes per row
    constexpr int RPW = 32 / C4;    // rows per warp
    int gt = blockIdx.x * blockDim.x + threadIdx.x;
    int w = gt >> 5;
    int lane = gt & 31;
    int sub = lane / C4;
    int lc  = lane % C4;
    int row = w * RPW + sub;
    if (row >= n) return;

    int beg = rowstart[row];
    int end = rowstart[row + 1];
    float4 acc = make_float4(0.f, 0.f, 0.f, 0.f);
    for (int e = beg; e < end; e++) {
        int s = esrc[e];
        float4 v = *((const float4*)(H + (size_t)s * C) + lc);
        acc.x += v.x; acc.y += v.y; acc.z += v.z; acc.w += v.w;
    }
    if (EPI) {
        float nd = ndst[row];
        float4 b = ((const float4*)bias)[lc];
        acc.x = fmaf(acc.x, nd, b.x);
        acc.y = fmaf(acc.y, nd, b.y);
        acc.z = fmaf(acc.z, nd, b.z);
        acc.w = fmaf(acc.w, nd, b.w);
    }
    *((float4*)(out + (size_t)row * C) + lc) = acc;
}

// ---------------- launch ----------------
extern "C" void kernel_launch(void* const* d_in, const int* in_sizes, int n_in,
                              void* d_out, int out_size)
{
    float *H, *AGG, *H2, *nsrc, *ndst;
    int *cnt, *outcnt, *rowstart, *esrc;
    cudaGetSymbolAddress((void**)&H,        g_H);
    cudaGetSymbolAddress((void**)&AGG,      g_AGG);
    cudaGetSymbolAddress((void**)&H2,       g_H2);
    cudaGetSymbolAddress((void**)&cnt,      g_cnt);
    cudaGetSymbolAddress((void**)&outcnt,   g_outcnt);
    cudaGetSymbolAddress((void**)&rowstart, g_rowstart);
    cudaGetSymbolAddress((void**)&esrc,     g_esrc);
    cudaGetSymbolAddress((void**)&nsrc,     g_nsrc);
    cudaGetSymbolAddress((void**)&ndst,     g_ndst);

    const float* W1 = (const float*)d_in[9];
    const float* b1 = (const float*)d_in[10];
    const float* W2 = (const float*)d_in[11];
    const float* b2 = (const float*)d_in[12];

    const int NB_N = (NNODES + 255) / 256;     // 391
    const int NB_E = (NEDGES + 255) / 256;     // 6250
    const int NB_G = (NNODES + 127) / 128;     // 782

    for (int g = 0; g < 3; g++) {
        const float* feat = (const float*)d_in[3 * g + 0];
        const int*   src  = (const int*)  d_in[3 * g + 1];
        const int*   dst  = (const int*)  d_in[3 * g + 2];
        float* out = (float*)d_out + (size_t)g * NNODES * FOUT;

        zero_kernel <<<NB_N, 256>>>(cnt, outcnt);
        hist_kernel <<<NB_E, 256>>>(src, dst, cnt, outcnt);
        scan_kernel <<<1, 1024>>>(cnt, rowstart);
        norms_kernel<<<NB_N, 256>>>(outcnt, rowstart, nsrc, ndst);
        fill_kernel <<<NB_E, 256>>>(src, dst, rowstart, cnt, esrc);

        // layer 1: H = (feat @ W1) * nsrc ; AGG = CSR-gather(H)
        gemm_tc<128, 0><<<NB_G, 256>>>(feat, W1, H, nsrc, nullptr, nullptr, NNODES);
        spmm_kernel<128, false><<<(NNODES * 32 + 255) / 256, 256>>>(
            H, rowstart, esrc, AGG, nullptr, nullptr, NNODES);

        // layer 2: H2 = (relu(AGG*ndst+b1) @ W2) * nsrc ; out = gather(H2)*ndst + b2
        gemm_tc<64, 1><<<NB_G, 256>>>(AGG, W2, H2, nsrc, ndst, b1, NNODES);
        spmm_kernel<64, true><<<(NNODES * 16 + 255) / 256, 256>>>(
            H2, rowstart, esrc, out, ndst, b2, NNODES);
    }
}

// round 3
// speedup vs baseline: 1.2605x; 1.2240x over previous
#include <cuda_runtime.h>
#include <cuda_bf16.h>
#include <cstdint>

#define NNODES 100000
#define NEDGES 1600000
#define FIN 128
#define FHID 128
#define FOUT 64

// ---------------- scratch (static device globals; no allocation) ----------------
__device__ float g_H  [(size_t)3 * NNODES * FHID];   // layer-1 transformed features (per graph)
__device__ float g_AGG[(size_t)3 * NNODES * FHID];   // layer-1 aggregate (per graph)
__device__ float g_H2 [(size_t)3 * NNODES * FOUT];   // layer-2 transformed features (per graph)
__device__ int   g_cnt     [3 * NNODES];             // in-degree histogram / fill cursor
__device__ int   g_outcnt  [3 * NNODES];             // out-degree histogram
__device__ int   g_rowstart[3 * (NNODES + 1)];       // CSR row offsets (by dst)
__device__ int   g_esrc    [3 * NEDGES];             // CSR column indices
__device__ float g_nsrc    [3 * NNODES];             // rsqrt(max(deg_out,1))
__device__ float g_ndst    [3 * NNODES];             // rsqrt(max(deg_in,1))

struct F3 { const float* p[3]; };
struct I3 { const int*   p[3]; };

// ---------------- helper kernels (batched across the 3 graphs) ----------------
__global__ void zero_all(int* cnt, int* outcnt) {
    int i = blockIdx.x * blockDim.x + threadIdx.x;
    if (i < 3 * NNODES) { cnt[i] = 0; outcnt[i] = 0; }
}

__global__ void hist_all(I3 srcs, I3 dsts, int* cnt, int* outcnt) {
    int g = blockIdx.y;
    int e = blockIdx.x * blockDim.x + threadIdx.x;
    if (e < NEDGES) {
        atomicAdd(&cnt   [g * NNODES + dsts.p[g][e]], 1);
        atomicAdd(&outcnt[g * NNODES + srcs.p[g][e]], 1);
    }
}

// one block per graph: exclusive scan of cnt -> rowstart; zeroes cnt for cursor reuse
__global__ void scan_all(int* __restrict__ cntAll, int* __restrict__ rowstartAll) {
    __shared__ int part[1024];
    int* cnt      = cntAll      + blockIdx.x * NNODES;
    int* rowstart = rowstartAll + blockIdx.x * (NNODES + 1);
    const int t = threadIdx.x;
    const int chunk = (NNODES + 1023) / 1024;   // 98
    const int lo = t * chunk;
    const int hi = min(lo + chunk, NNODES);
    int s = 0;
    for (int i = lo; i < hi; i++) s += cnt[i];
    part[t] = s;
    __syncthreads();
    for (int off = 1; off < 1024; off <<= 1) {
        int v = (t >= off) ? part[t - off] : 0;
        __syncthreads();
        part[t] += v;
        __syncthreads();
    }
    int run = part[t] - s;  // exclusive prefix
    for (int i = lo; i < hi; i++) {
        rowstart[i] = run;
        run += cnt[i];
        cnt[i] = 0;
    }
    if (t == 1023) rowstart[NNODES] = part[1023];
}

__global__ void norms_all(const int* __restrict__ outcnt,
                          const int* __restrict__ rowstartAll,
                          float* nsrc, float* ndst) {
    int i = blockIdx.x * blockDim.x + threadIdx.x;
    if (i < 3 * NNODES) {
        int g = i / NNODES, r = i - g * NNODES;
        const int* rowstart = rowstartAll + g * (NNODES + 1);
        nsrc[i] = rsqrtf(fmaxf((float)outcnt[i], 1.f));
        ndst[i] = rsqrtf(fmaxf((float)(rowstart[r + 1] - rowstart[r]), 1.f));
    }
}

__global__ void fill_all(I3 srcs, I3 dsts, const int* __restrict__ rowstartAll,
                         int* cnt, int* __restrict__ esrcAll) {
    int g = blockIdx.y;
    int e = blockIdx.x * blockDim.x + threadIdx.x;
    if (e < NEDGES) {
        int d = dsts.p[g][e];
        int pos = rowstartAll[g * (NNODES + 1) + d] + atomicAdd(&cnt[g * NNODES + d], 1);
        esrcAll[g * NEDGES + pos] = srcs.p[g][e];
    }
}

// ---------------- bf16 split helpers ----------------
__device__ __forceinline__ void split2(float f0, float f1, uint32_t& uh, uint32_t& ul) {
    __nv_bfloat16 h0 = __float2bfloat16_rn(f0), h1 = __float2bfloat16_rn(f1);
    float r0 = f0 - __bfloat162float(h0);
    float r1 = f1 - __bfloat162float(h1);
    __nv_bfloat16 l0 = __float2bfloat16_rn(r0), l1 = __float2bfloat16_rn(r1);
    uh = ((uint32_t)(*(uint16_t*)&h1) << 16) | (uint32_t)(*(uint16_t*)&h0);
    ul = ((uint32_t)(*(uint16_t*)&l1) << 16) | (uint32_t)(*(uint16_t*)&l0);
}

__device__ __forceinline__ void mma_bf16(float* d, const uint32_t* a, const uint32_t* b) {
    asm volatile(
        "mma.sync.aligned.m16n8k16.row.col.f32.bf16.bf16.f32 "
        "{%0,%1,%2,%3},{%4,%5,%6,%7},{%8,%9},{%0,%1,%2,%3};"
        : "+f"(d[0]), "+f"(d[1]), "+f"(d[2]), "+f"(d[3])
        : "r"(a[0]), "r"(a[1]), "r"(a[2]), "r"(a[3]), "r"(b[0]), "r"(b[1]));
}

// ---------------- tensor-core GEMM (M x 128) @ (128 x BN), 3-term bf16 split ----------------
// grid: (ceil(M/128), 3)  -- one y-slice per graph
// MODE 0: a = A[i,k]                     (layer-1: feat)
// MODE 1: a = relu(A[i,k]*ndst[i]+b1[k]) (layer-2: aggregate transform)
// epilogue: C[i,:] = dot * nsrc[i]
template <int BN, int MODE>
__global__ __launch_bounds__(256)
void gemm_bf16x3(F3 Aall,
                 const float* __restrict__ B,
                 float* __restrict__ Cbase,
                 const float* __restrict__ nsrcAll,
                 const float* __restrict__ ndstAll,
                 const float* __restrict__ bias)
{
    constexpr int BM = 128, BK = 16;
    constexpr int LDAp = 12;                     // packed words/row (8 data + 4 pad)
    constexpr int LDBp = BN + 8;                 // packed words/row
    constexpr int WN  = (BN == 128) ? 64 : 32;
    constexpr int NT  = WN / 8;

    __shared__ uint32_t Ahp[BM][LDAp];
    __shared__ uint32_t Alp[BM][LDAp];
    __shared__ uint32_t Bhp[BK / 2][LDBp];
    __shared__ uint32_t Blp[BK / 2][LDBp];
    __shared__ float bsh[FHID];

    const int gidx = blockIdx.y;
    const float* A = Aall.p[gidx];
    float* C = Cbase + (size_t)gidx * NNODES * BN;
    const float* nsrc = nsrcAll + gidx * NNODES;
    const float* ndst = (MODE == 1) ? (ndstAll + gidx * NNODES) : nullptr;

    const int tid  = threadIdx.x;
    const int warp = tid >> 5;
    const int lane = tid & 31;
    const int warp_m = warp & 3;
    const int warp_n = warp >> 2;
    const int m0w = warp_m * 32;
    const int n0w = warp_n * WN;
    const int g  = lane >> 2;
    const int tg = lane & 3;
    const int blockRow = blockIdx.x * BM;
    const int M = NNODES;

    if (MODE == 1 && tid < FHID) bsh[tid] = bias[tid];

    float acc[2][NT][4];
#pragma unroll
    for (int mi = 0; mi < 2; mi++)
#pragma unroll
        for (int ni = 0; ni < NT; ni++)
#pragma unroll
            for (int j = 0; j < 4; j++) acc[mi][ni][j] = 0.f;

    const int arow = tid >> 2;          // 0..63
    const int acol = tid & 3;           // float4 column (4 k each)

    for (int kc = 0; kc < FIN; kc += BK) {
        __syncthreads();
        // ---- A tile: 128 rows x 16 k, bf16 hi/lo split, packed pairs along k ----
#pragma unroll
        for (int it = 0; it < 2; it++) {
            int row  = arow + 64 * it;
            int grow = blockRow + row;
            float4 v = make_float4(0.f, 0.f, 0.f, 0.f);
            if (grow < M) {
                v = *(const float4*)(A + (size_t)grow * FIN + kc + acol * 4);
                if (MODE == 1) {
                    float nd = ndst[grow];
                    v.x = fmaxf(fmaf(v.x, nd, bsh[kc + acol * 4 + 0]), 0.f);
                    v.y = fmaxf(fmaf(v.y, nd, bsh[kc + acol * 4 + 1]), 0.f);
                    v.z = fmaxf(fmaf(v.z, nd, bsh[kc + acol * 4 + 2]), 0.f);
                    v.w = fmaxf(fmaf(v.w, nd, bsh[kc + acol * 4 + 3]), 0.f);
                }
            }
            uint32_t uh0, ul0, uh1, ul1;
            split2(v.x, v.y, uh0, ul0);
            split2(v.z, v.w, uh1, ul1);
            Ahp[row][acol * 2 + 0] = uh0;  Alp[row][acol * 2 + 0] = ul0;
            Ahp[row][acol * 2 + 1] = uh1;  Alp[row][acol * 2 + 1] = ul1;
        }
        // ---- B tile: 16 k x BN, vertical pack (k pairs) ----
        {
            constexpr int ITEMS = (BK / 2) * (BN / 4);   // 256 (BN=128) or 128 (BN=64)
            int idx = tid;
            if (ITEMS == 256 || tid < ITEMS) {
                int jp = idx / (BN / 4);     // k-pair 0..7
                int nq = idx % (BN / 4);     // n quad
                float4 r0 = *(const float4*)(B + (size_t)(kc + 2 * jp + 0) * BN + nq * 4);
                float4 r1 = *(const float4*)(B + (size_t)(kc + 2 * jp + 1) * BN + nq * 4);
                uint32_t h[4], l[4];
                split2(r0.x, r1.x, h[0], l[0]);
                split2(r0.y, r1.y, h[1], l[1]);
                split2(r0.z, r1.z, h[2], l[2]);
                split2(r0.w, r1.w, h[3], l[3]);
                *(uint4*)&Bhp[jp][nq * 4] = make_uint4(h[0], h[1], h[2], h[3]);
                *(uint4*)&Blp[jp][nq * 4] = make_uint4(l[0], l[1], l[2], l[3]);
            }
        }
        __syncthreads();

        // ---- fragments + 3-term MMA (one m16n8k16 step per tile) ----
        uint32_t ah[2][4], al[2][4];
#pragma unroll
        for (int mi = 0; mi < 2; mi++) {
            int r = m0w + mi * 16 + g;
            ah[mi][0] = Ahp[r][tg];          al[mi][0] = Alp[r][tg];
            ah[mi][1] = Ahp[r + 8][tg];      al[mi][1] = Alp[r + 8][tg];
            ah[mi][2] = Ahp[r][tg + 4];      al[mi][2] = Alp[r][tg + 4];
            ah[mi][3] = Ahp[r + 8][tg + 4];  al[mi][3] = Alp[r + 8][tg + 4];
        }
        uint32_t bh[NT][2], bl[NT][2];
#pragma unroll
        for (int ni = 0; ni < NT; ni++) {
            int c = n0w + ni * 8 + g;
            bh[ni][0] = Bhp[tg][c];          bl[ni][0] = Blp[tg][c];
            bh[ni][1] = Bhp[tg + 4][c];      bl[ni][1] = Blp[tg + 4][c];
        }
#pragma unroll
        for (int mi = 0; mi < 2; mi++)
#pragma unroll
            for (int ni = 0; ni < NT; ni++) {
                mma_bf16(acc[mi][ni], al[mi], bh[ni]);   // lo*hi
                mma_bf16(acc[mi][ni], ah[mi], bl[ni]);   // hi*lo
                mma_bf16(acc[mi][ni], ah[mi], bh[ni]);   // hi*hi
            }
    }

    // ---- epilogue: C[i,:] = acc * nsrc[i] ----
#pragma unroll
    for (int mi = 0; mi < 2; mi++) {
        int r0 = blockRow + m0w + mi * 16 + g;
        int r1 = r0 + 8;
        float s0 = (r0 < M) ? nsrc[r0] : 0.f;
        float s1 = (r1 < M) ? nsrc[r1] : 0.f;
#pragma unroll
        for (int ni = 0; ni < NT; ni++) {
            int col = n0w + ni * 8 + 2 * tg;
            if (r0 < M)
                *(float2*)(C + (size_t)r0 * BN + col) =
                    make_float2(acc[mi][ni][0] * s0, acc[mi][ni][1] * s0);
            if (r1 < M)
                *(float2*)(C + (size_t)r1 * BN + col) =
                    make_float2(acc[mi][ni][2] * s1, acc[mi][ni][3] * s1);
        }
    }
}

// ---------------- gather SpMM (batched): out[i,:] = sum_{e in row i} H[esrc[e],:] ----------------
template <int C, bool EPI>
__global__ void spmm_all(const float* __restrict__ Hbase,
                         const int* __restrict__ rowstartAll,
                         const int* __restrict__ esrcAll,
                         float* __restrict__ outBase,
                         const float* __restrict__ ndstAll,
                         const float* __restrict__ bias)
{
    constexpr int C4  = C / 4;
    constexpr int RPW = 32 / C4;
    const int gidx = blockIdx.y;
    const float* H = Hbase + (size_t)gidx * NNODES * C;
    const int* rowstart = rowstartAll + gidx * (NNODES + 1);
    const int* esrc = esrcAll + (size_t)gidx * NEDGES;
    float* out = outBase + (size_t)gidx * NNODES * C;

    int gt = blockIdx.x * blockDim.x + threadIdx.x;
    int w = gt >> 5;
    int lane = gt & 31;
    int sub = lane / C4;
    int lc  = lane % C4;
    int row = w * RPW + sub;
    if (row >= NNODES) return;

    int beg = rowstart[row];
    int end = rowstart[row + 1];
    float4 acc = make_float4(0.f, 0.f, 0.f, 0.f);
    int e = beg;
    for (; e + 4 <= end; e += 4) {
        int s0 = __ldg(esrc + e + 0);
        int s1 = __ldg(esrc + e + 1);
        int s2 = __ldg(esrc + e + 2);
        int s3 = __ldg(esrc + e + 3);
        float4 v0 = __ldg((const float4*)(H + (size_t)s0 * C) + lc);
        float4 v1 = __ldg((const float4*)(H + (size_t)s1 * C) + lc);
        float4 v2 = __ldg((const float4*)(H + (size_t)s2 * C) + lc);
        float4 v3 = __ldg((const float4*)(H + (size_t)s3 * C) + lc);
        acc.x += v0.x + v1.x + v2.x + v3.x;
        acc.y += v0.y + v1.y + v2.y + v3.y;
        acc.z += v0.z + v1.z + v2.z + v3.z;
        acc.w += v0.w + v1.w + v2.w + v3.w;
    }
    for (; e < end; e++) {
        int s = __ldg(esrc + e);
        float4 v = __ldg((const float4*)(H + (size_t)s * C) + lc);
        acc.x += v.x; acc.y += v.y; acc.z += v.z; acc.w += v.w;
    }
    if (EPI) {
        float nd = ndstAll[gidx * NNODES + row];
        float4 b = ((const float4*)bias)[lc];
        acc.x = fmaf(acc.x, nd, b.x);
        acc.y = fmaf(acc.y, nd, b.y);
        acc.z = fmaf(acc.z, nd, b.z);
        acc.w = fmaf(acc.w, nd, b.w);
    }
    *((float4*)(out + (size_t)row * C) + lc) = acc;
}

// ---------------- launch ----------------
extern "C" void kernel_launch(void* const* d_in, const int* in_sizes, int n_in,
                              void* d_out, int out_size)
{
    float *H, *AGG, *H2, *nsrc, *ndst;
    int *cnt, *outcnt, *rowstart, *esrc;
    cudaGetSymbolAddress((void**)&H,        g_H);
    cudaGetSymbolAddress((void**)&AGG,      g_AGG);
    cudaGetSymbolAddress((void**)&H2,       g_H2);
    cudaGetSymbolAddress((void**)&cnt,      g_cnt);
    cudaGetSymbolAddress((void**)&outcnt,   g_outcnt);
    cudaGetSymbolAddress((void**)&rowstart, g_rowstart);
    cudaGetSymbolAddress((void**)&esrc,     g_esrc);
    cudaGetSymbolAddress((void**)&nsrc,     g_nsrc);
    cudaGetSymbolAddress((void**)&ndst,     g_ndst);

    F3 feats = {{ (const float*)d_in[0], (const float*)d_in[3], (const float*)d_in[6] }};
    I3 srcs  = {{ (const int*)d_in[1],   (const int*)d_in[4],   (const int*)d_in[7] }};
    I3 dsts  = {{ (const int*)d_in[2],   (const int*)d_in[5],   (const int*)d_in[8] }};
    const float* W1 = (const float*)d_in[9];
    const float* b1 = (const float*)d_in[10];
    const float* W2 = (const float*)d_in[11];
    const float* b2 = (const float*)d_in[12];

    F3 aggs = {{ AGG, AGG + (size_t)NNODES * FHID, AGG + (size_t)2 * NNODES * FHID }};

    dim3 gE((NEDGES + 255) / 256, 3);
    dim3 gG((NNODES + 127) / 128, 3);
    dim3 gS1((NNODES * 32 + 255) / 256, 3);
    dim3 gS2((NNODES * 16 + 255) / 256, 3);

    zero_all <<<(3 * NNODES + 255) / 256, 256>>>(cnt, outcnt);
    hist_all <<<gE, 256>>>(srcs, dsts, cnt, outcnt);
    scan_all <<<3, 1024>>>(cnt, rowstart);
    norms_all<<<(3 * NNODES + 255) / 256, 256>>>(outcnt, rowstart, nsrc, ndst);
    fill_all <<<gE, 256>>>(srcs, dsts, rowstart, cnt, esrc);

    // layer 1: H = (feat @ W1) * nsrc ; AGG = CSR-gather(H)
    gemm_bf16x3<128, 0><<<gG, 256>>>(feats, W1, H, nsrc, nullptr, nullptr);
    spmm_all<128, false><<<gS1, 256>>>(H, rowstart, esrc, AGG, nullptr, nullptr);

    // layer 2: H2 = (relu(AGG*ndst+b1) @ W2) * nsrc ; out = gather(H2)*ndst + b2
    gemm_bf16x3<64, 1><<<gG, 256>>>(aggs, W2, H2, nsrc, ndst, b1);
    spmm_all<64, true><<<gS2, 256>>>(H2, rowstart, esrc, (float*)d_out, ndst, b2);
}

// round 4
// speedup vs baseline: 1.3900x; 1.1028x over previous
#include <cuda_runtime.h>
#include <cuda_bf16.h>
#include <cstdint>

#define NNODES 100000
#define NEDGES 1600000
#define FIN 128
#define FHID 128
#define FOUT 64

// ---------------- scratch (static device globals; no allocation) ----------------
__device__ float    g_XS [(size_t)3 * NNODES * FIN];    // scaled-aggregated inputs (per graph)
__device__ float    g_H2 [(size_t)3 * NNODES * FOUT];   // layer-2 transformed features
__device__ int      g_cnt     [3 * NNODES];
__device__ int      g_outcnt  [3 * NNODES];
__device__ int      g_rowstart[3 * (NNODES + 1)];
__device__ int      g_esrc    [3 * NEDGES];
__device__ float    g_nsrc    [3 * NNODES];
__device__ float    g_ndst    [3 * NNODES];
__device__ uint32_t g_W1h[64 * 128], g_W1l[64 * 128];   // W1 packed bf16 hi/lo (k-pairs)
__device__ uint32_t g_W2h[64 * 64],  g_W2l[64 * 64];    // W2 packed bf16 hi/lo

struct F3 { const float* p[3]; };
struct I3 { const int*   p[3]; };

// ---------------- helper kernels (batched across the 3 graphs) ----------------
__global__ void zero_all(int* cnt, int* outcnt) {
    int i = blockIdx.x * blockDim.x + threadIdx.x;
    if (i < 3 * NNODES) { cnt[i] = 0; outcnt[i] = 0; }
}

__global__ void hist_all(I3 srcs, I3 dsts, int* cnt, int* outcnt) {
    int g = blockIdx.y;
    int e = blockIdx.x * blockDim.x + threadIdx.x;
    if (e < NEDGES) {
        atomicAdd(&cnt   [g * NNODES + dsts.p[g][e]], 1);
        atomicAdd(&outcnt[g * NNODES + srcs.p[g][e]], 1);
    }
}

__global__ void scan_all(int* __restrict__ cntAll, int* __restrict__ rowstartAll) {
    __shared__ int part[1024];
    int* cnt      = cntAll      + blockIdx.x * NNODES;
    int* rowstart = rowstartAll + blockIdx.x * (NNODES + 1);
    const int t = threadIdx.x;
    const int chunk = (NNODES + 1023) / 1024;
    const int lo = t * chunk;
    const int hi = min(lo + chunk, NNODES);
    int s = 0;
    for (int i = lo; i < hi; i++) s += cnt[i];
    part[t] = s;
    __syncthreads();
    for (int off = 1; off < 1024; off <<= 1) {
        int v = (t >= off) ? part[t - off] : 0;
        __syncthreads();
        part[t] += v;
        __syncthreads();
    }
    int run = part[t] - s;
    for (int i = lo; i < hi; i++) {
        rowstart[i] = run;
        run += cnt[i];
        cnt[i] = 0;
    }
    if (t == 1023) rowstart[NNODES] = part[1023];
}

__global__ void norms_all(const int* __restrict__ outcnt,
                          const int* __restrict__ rowstartAll,
                          float* nsrc, float* ndst) {
    int i = blockIdx.x * blockDim.x + threadIdx.x;
    if (i < 3 * NNODES) {
        int g = i / NNODES, r = i - g * NNODES;
        const int* rowstart = rowstartAll + g * (NNODES + 1);
        nsrc[i] = rsqrtf(fmaxf((float)outcnt[i], 1.f));
        ndst[i] = rsqrtf(fmaxf((float)(rowstart[r + 1] - rowstart[r]), 1.f));
    }
}

__global__ void fill_all(I3 srcs, I3 dsts, const int* __restrict__ rowstartAll,
                         int* cnt, int* __restrict__ esrcAll) {
    int g = blockIdx.y;
    int e = blockIdx.x * blockDim.x + threadIdx.x;
    if (e < NEDGES) {
        int d = dsts.p[g][e];
        int pos = rowstartAll[g * (NNODES + 1) + d] + atomicAdd(&cnt[g * NNODES + d], 1);
        esrcAll[g * NEDGES + pos] = srcs.p[g][e];
    }
}

// ---------------- bf16 split helpers ----------------
__device__ __forceinline__ void split2(float f0, float f1, uint32_t& uh, uint32_t& ul) {
    __nv_bfloat16 h0 = __float2bfloat16_rn(f0), h1 = __float2bfloat16_rn(f1);
    float r0 = f0 - __bfloat162float(h0);
    float r1 = f1 - __bfloat162float(h1);
    __nv_bfloat16 l0 = __float2bfloat16_rn(r0), l1 = __float2bfloat16_rn(r1);
    uh = ((uint32_t)(*(uint16_t*)&h1) << 16) | (uint32_t)(*(uint16_t*)&h0);
    ul = ((uint32_t)(*(uint16_t*)&l1) << 16) | (uint32_t)(*(uint16_t*)&l0);
}

__device__ __forceinline__ void mma_bf16(float* d, const uint32_t* a, const uint32_t* b) {
    asm volatile(
        "mma.sync.aligned.m16n8k16.row.col.f32.bf16.bf16.f32 "
        "{%0,%1,%2,%3},{%4,%5,%6,%7},{%8,%9},{%0,%1,%2,%3};"
        : "+f"(d[0]), "+f"(d[1]), "+f"(d[2]), "+f"(d[3])
        : "r"(a[0]), "r"(a[1]), "r"(a[2]), "r"(a[3]), "r"(b[0]), "r"(b[1]));
}

// ---------------- pack W1/W2 to bf16 hi/lo (k-pair packed) ----------------
__global__ void packW(const float* __restrict__ W1, const float* __restrict__ W2,
                      uint32_t* w1h, uint32_t* w1l, uint32_t* w2h, uint32_t* w2l) {
    int i = blockIdx.x * blockDim.x + threadIdx.x;
    if (i < 64 * 128) {
        int kp = i >> 7, c = i & 127;
        split2(W1[(2 * kp) * FHID + c], W1[(2 * kp + 1) * FHID + c], w1h[i], w1l[i]);
    }
    if (i < 64 * 64) {
        int kp = i >> 6, c = i & 63;
        split2(W2[(2 * kp) * FOUT + c], W2[(2 * kp + 1) * FOUT + c], w2h[i], w2l[i]);
    }
}

// ---------------- scaled gather SpMM: XS[i,:] = sum_{e in row i} nsrc[s]*feat[s,:] ----------------
__global__ void spmm_scaled(F3 feats,
                            const int* __restrict__ rowstartAll,
                            const int* __restrict__ esrcAll,
                            float* __restrict__ XSbase,
                            const float* __restrict__ nsrcAll)
{
    const int gidx = blockIdx.y;
    const float* X = feats.p[gidx];
    const float* nsrc = nsrcAll + gidx * NNODES;
    const int* rowstart = rowstartAll + gidx * (NNODES + 1);
    const int* esrc = esrcAll + (size_t)gidx * NEDGES;
    float* XS = XSbase + (size_t)gidx * NNODES * FIN;

    int gt = blockIdx.x * blockDim.x + threadIdx.x;
    int w = gt >> 5;          // warp id == row
    int lc = gt & 31;         // float4 lane (32 x 4 = 128 cols)
    int row = w;
    if (row >= NNODES) return;

    int beg = rowstart[row];
    int end = rowstart[row + 1];
    float4 acc = make_float4(0.f, 0.f, 0.f, 0.f);
    int e = beg;
    for (; e + 4 <= end; e += 4) {
        int s0 = __ldg(esrc + e + 0);
        int s1 = __ldg(esrc + e + 1);
        int s2 = __ldg(esrc + e + 2);
        int s3 = __ldg(esrc + e + 3);
        float w0 = __ldg(nsrc + s0), w1 = __ldg(nsrc + s1);
        float w2 = __ldg(nsrc + s2), w3 = __ldg(nsrc + s3);
        float4 v0 = __ldg((const float4*)(X + (size_t)s0 * FIN) + lc);
        float4 v1 = __ldg((const float4*)(X + (size_t)s1 * FIN) + lc);
        float4 v2 = __ldg((const float4*)(X + (size_t)s2 * FIN) + lc);
        float4 v3 = __ldg((const float4*)(X + (size_t)s3 * FIN) + lc);
        acc.x = fmaf(w0, v0.x, fmaf(w1, v1.x, fmaf(w2, v2.x, fmaf(w3, v3.x, acc.x))));
        acc.y = fmaf(w0, v0.y, fmaf(w1, v1.y, fmaf(w2, v2.y, fmaf(w3, v3.y, acc.y))));
        acc.z = fmaf(w0, v0.z, fmaf(w1, v1.z, fmaf(w2, v2.z, fmaf(w3, v3.z, acc.z))));
        acc.w = fmaf(w0, v0.w, fmaf(w1, v1.w, fmaf(w2, v2.w, fmaf(w3, v3.w, acc.w))));
    }
    for (; e < end; e++) {
        int s = __ldg(esrc + e);
        float ws = __ldg(nsrc + s);
        float4 v = __ldg((const float4*)(X + (size_t)s * FIN) + lc);
        acc.x = fmaf(ws, v.x, acc.x);
        acc.y = fmaf(ws, v.y, acc.y);
        acc.z = fmaf(ws, v.z, acc.z);
        acc.w = fmaf(ws, v.w, acc.w);
    }
    *((float4*)(XS + (size_t)row * FIN) + lc) = acc;
}

// ---------------- fused dense chain ----------------
// H2 = relu( (XS @ W1) * ndst + b1 ) @ W2 * nsrc
// grid (ceil(N/128), 3), block 256, dynamic smem
// smem u32 layout offsets:
#define LDAp 12
#define LDB1 136
#define LDT  68
#define LDB2 72
#define OFF_AH 0
#define OFF_AL (OFF_AH + 128 * LDAp)
#define OFF_B1H (OFF_AL + 128 * LDAp)
#define OFF_B1L (OFF_B1H + 8 * LDB1)
#define OFF_TH (OFF_B1L + 8 * LDB1)
#define OFF_TL (OFF_TH + 128 * LDT)
#define OFF_B2H (OFF_TL + 128 * LDT)
#define OFF_B2L (OFF_B2H + 8 * LDB2)
#define OFF_BSH (OFF_B2L + 8 * LDB2)
#define SMEM_WORDS (OFF_BSH + 128)

__global__ __launch_bounds__(256)
void fused_gemm(const float* __restrict__ XSbase,
                const uint32_t* __restrict__ W1h, const uint32_t* __restrict__ W1l,
                const uint32_t* __restrict__ W2h, const uint32_t* __restrict__ W2l,
                const float* __restrict__ b1,
                float* __restrict__ H2base,
                const float* __restrict__ nsrcAll,
                const float* __restrict__ ndstAll)
{
    extern __shared__ uint32_t sm[];
    uint32_t* Ahp = sm + OFF_AH;    // [128][LDAp]
    uint32_t* Alp = sm + OFF_AL;
    uint32_t* B1h = sm + OFF_B1H;   // [8][LDB1]
    uint32_t* B1l = sm + OFF_B1L;
    uint32_t* Th  = sm + OFF_TH;    // [128][LDT]
    uint32_t* Tl  = sm + OFF_TL;
    uint32_t* B2h = sm + OFF_B2H;   // [8][LDB2]
    uint32_t* B2l = sm + OFF_B2L;
    float*    bsh = (float*)(sm + OFF_BSH);

    const int gidx = blockIdx.y;
    const float* XS   = XSbase + (size_t)gidx * NNODES * FIN;
    float*       H2   = H2base + (size_t)gidx * NNODES * FOUT;
    const float* nsrc = nsrcAll + gidx * NNODES;
    const float* ndst = ndstAll + gidx * NNODES;

    const int tid  = threadIdx.x;
    const int warp = tid >> 5;
    const int lane = tid & 31;
    const int warp_m = warp & 3;
    const int warp_n = warp >> 2;
    const int m0w = warp_m * 32;
    const int g  = lane >> 2;
    const int tg = lane & 3;
    const int blockRow = blockIdx.x * 128;
    const int M = NNODES;

    if (tid < FHID) bsh[tid] = b1[tid];

    // ================= stage 1: T = XS @ W1 (3-term bf16) =================
    float acc1[2][8][4];
#pragma unroll
    for (int mi = 0; mi < 2; mi++)
#pragma unroll
        for (int ni = 0; ni < 8; ni++)
#pragma unroll
            for (int j = 0; j < 4; j++) acc1[mi][ni][j] = 0.f;

    const int n0w1 = warp_n * 64;
    const int arow = tid >> 2;
    const int acol = tid & 3;

    for (int kc = 0; kc < FIN; kc += 16) {
        __syncthreads();
        // A chunk: 128 rows x 16 k
#pragma unroll
        for (int it = 0; it < 2; it++) {
            int row  = arow + 64 * it;
            int grow = blockRow + row;
            float4 v = make_float4(0.f, 0.f, 0.f, 0.f);
            if (grow < M)
                v = *(const float4*)(XS + (size_t)grow * FIN + kc + acol * 4);
            uint32_t uh0, ul0, uh1, ul1;
            split2(v.x, v.y, uh0, ul0);
            split2(v.z, v.w, uh1, ul1);
            Ahp[row * LDAp + acol * 2 + 0] = uh0;  Alp[row * LDAp + acol * 2 + 0] = ul0;
            Ahp[row * LDAp + acol * 2 + 1] = uh1;  Alp[row * LDAp + acol * 2 + 1] = ul1;
        }
        // B1 chunk: 8 k-pairs x 128 cols (pre-packed)
        {
            int jp = tid >> 5;            // 0..7
            int c4 = (tid & 31) * 4;
            const uint32_t* src_h = W1h + (size_t)(kc / 2 + jp) * FHID + c4;
            const uint32_t* src_l = W1l + (size_t)(kc / 2 + jp) * FHID + c4;
            *(uint4*)&B1h[jp * LDB1 + c4] = *(const uint4*)src_h;
            *(uint4*)&B1l[jp * LDB1 + c4] = *(const uint4*)src_l;
        }
        __syncthreads();

        uint32_t ah[2][4], al[2][4];
#pragma unroll
        for (int mi = 0; mi < 2; mi++) {
            int r = m0w + mi * 16 + g;
            ah[mi][0] = Ahp[r * LDAp + tg];            al[mi][0] = Alp[r * LDAp + tg];
            ah[mi][1] = Ahp[(r + 8) * LDAp + tg];      al[mi][1] = Alp[(r + 8) * LDAp + tg];
            ah[mi][2] = Ahp[r * LDAp + tg + 4];        al[mi][2] = Alp[r * LDAp + tg + 4];
            ah[mi][3] = Ahp[(r + 8) * LDAp + tg + 4];  al[mi][3] = Alp[(r + 8) * LDAp + tg + 4];
        }
#pragma unroll
        for (int ni = 0; ni < 8; ni++) {
            int c = n0w1 + ni * 8 + g;
            uint32_t bh[2], bl[2];
            bh[0] = B1h[tg * LDB1 + c];        bl[0] = B1l[tg * LDB1 + c];
            bh[1] = B1h[(tg + 4) * LDB1 + c];  bl[1] = B1l[(tg + 4) * LDB1 + c];
#pragma unroll
            for (int mi = 0; mi < 2; mi++) {
                mma_bf16(acc1[mi][ni], al[mi], bh);
                mma_bf16(acc1[mi][ni], ah[mi], bl);
                mma_bf16(acc1[mi][ni], ah[mi], bh);
            }
        }
    }

    // ---- t = relu(T*ndst + b1), packed bf16 hi/lo into smem ----
    __syncthreads();   // stage-1 frag reads done before T overwrites A? (separate buffers; sync for B1 reuse safety)
#pragma unroll
    for (int mi = 0; mi < 2; mi++) {
        int r0 = m0w + mi * 16 + g;
        int r1 = r0 + 8;
        int gr0 = blockRow + r0, gr1 = blockRow + r1;
        float nd0 = (gr0 < M) ? ndst[gr0] : 0.f;
        float nd1 = (gr1 < M) ? ndst[gr1] : 0.f;
#pragma unroll
        for (int ni = 0; ni < 8; ni++) {
            int col = n0w1 + ni * 8 + 2 * tg;
            int cp  = col >> 1;   // k-pair index in T
            float t00 = fmaxf(fmaf(acc1[mi][ni][0], nd0, bsh[col]), 0.f);
            float t01 = fmaxf(fmaf(acc1[mi][ni][1], nd0, bsh[col + 1]), 0.f);
            float t10 = fmaxf(fmaf(acc1[mi][ni][2], nd1, bsh[col]), 0.f);
            float t11 = fmaxf(fmaf(acc1[mi][ni][3], nd1, bsh[col + 1]), 0.f);
            uint32_t h, l;
            split2(t00, t01, h, l);
            Th[r0 * LDT + cp] = h;  Tl[r0 * LDT + cp] = l;
            split2(t10, t11, h, l);
            Th[r1 * LDT + cp] = h;  Tl[r1 * LDT + cp] = l;
        }
    }

    // ================= stage 2: H2 = t @ W2 * nsrc =================
    float acc2[2][4][4];
#pragma unroll
    for (int mi = 0; mi < 2; mi++)
#pragma unroll
        for (int ni = 0; ni < 4; ni++)
#pragma unroll
            for (int j = 0; j < 4; j++) acc2[mi][ni][j] = 0.f;

    const int n0w2 = warp_n * 32;

    for (int ch = 0; ch < 8; ch++) {
        __syncthreads();
        // B2 chunk: k-pairs ch*8..ch*8+7, 64 cols
        if (tid < 128) {
            int jp = tid >> 4;
            int c4 = (tid & 15) * 4;
            *(uint4*)&B2h[jp * LDB2 + c4] =
                *(const uint4*)(W2h + (size_t)(ch * 8 + jp) * FOUT + c4);
        } else {
            int t2 = tid - 128;
            int jp = t2 >> 4;
            int c4 = (t2 & 15) * 4;
            *(uint4*)&B2l[jp * LDB2 + c4] =
                *(const uint4*)(W2l + (size_t)(ch * 8 + jp) * FOUT + c4);
        }
        __syncthreads();

        int cb = ch * 8;
        uint32_t ah[2][4], al[2][4];
#pragma unroll
        for (int mi = 0; mi < 2; mi++) {
            int r = m0w + mi * 16 + g;
            ah[mi][0] = Th[r * LDT + cb + tg];            al[mi][0] = Tl[r * LDT + cb + tg];
            ah[mi][1] = Th[(r + 8) * LDT + cb + tg];      al[mi][1] = Tl[(r + 8) * LDT + cb + tg];
            ah[mi][2] = Th[r * LDT + cb + tg + 4];        al[mi][2] = Tl[r * LDT + cb + tg + 4];
            ah[mi][3] = Th[(r + 8) * LDT + cb + tg + 4];  al[mi][3] = Tl[(r + 8) * LDT + cb + tg + 4];
        }
#pragma unroll
        for (int ni = 0; ni < 4; ni++) {
            int c = n0w2 + ni * 8 + g;
            uint32_t bh[2], bl[2];
            bh[0] = B2h[tg * LDB2 + c];        bl[0] = B2l[tg * LDB2 + c];
            bh[1] = B2h[(tg + 4) * LDB2 + c];  bl[1] = B2l[(tg + 4) * LDB2 + c];
#pragma unroll
            for (int mi = 0; mi < 2; mi++) {
                mma_bf16(acc2[mi][ni], al[mi], bh);
                mma_bf16(acc2[mi][ni], ah[mi], bl);
                mma_bf16(acc2[mi][ni], ah[mi], bh);
            }
        }
    }

    // ---- epilogue: H2 = acc2 * nsrc ----
#pragma unroll
    for (int mi = 0; mi < 2; mi++) {
        int gr0 = blockRow + m0w + mi * 16 + g;
        int gr1 = gr0 + 8;
        float s0 = (gr0 < M) ? nsrc[gr0] : 0.f;
        float s1 = (gr1 < M) ? nsrc[gr1] : 0.f;
#pragma unroll
        for (int ni = 0; ni < 4; ni++) {
            int col = n0w2 + ni * 8 + 2 * tg;
            if (gr0 < M)
                *(float2*)(H2 + (size_t)gr0 * FOUT + col) =
                    make_float2(acc2[mi][ni][0] * s0, acc2[mi][ni][1] * s0);
            if (gr1 < M)
                *(float2*)(H2 + (size_t)gr1 * FOUT + col) =
                    make_float2(acc2[mi][ni][2] * s1, acc2[mi][ni][3] * s1);
        }
    }
}

// ---------------- final gather SpMM: out = gather(H2)*ndst + b2 ----------------
__global__ void spmm_out(const float* __restrict__ H2base,
                         const int* __restrict__ rowstartAll,
                         const int* __restrict__ esrcAll,
                         float* __restrict__ outBase,
                         const float* __restrict__ ndstAll,
                         const float* __restrict__ bias)
{
    constexpr int C = FOUT, C4 = C / 4, RPW = 32 / C4;   // 16 lanes/row, 2 rows/warp
    const int gidx = blockIdx.y;
    const float* H = H2base + (size_t)gidx * NNODES * C;
    const int* rowstart = rowstartAll + gidx * (NNODES + 1);
    const int* esrc = esrcAll + (size_t)gidx * NEDGES;
    float* out = outBase + (size_t)gidx * NNODES * C;

    int gt = blockIdx.x * blockDim.x + threadIdx.x;
    int w = gt >> 5;
    int lane = gt & 31;
    int sub = lane / C4;
    int lc  = lane % C4;
    int row = w * RPW + sub;
    if (row >= NNODES) return;

    int beg = rowstart[row];
    int end = rowstart[row + 1];
    float4 acc = make_float4(0.f, 0.f, 0.f, 0.f);
    int e = beg;
    for (; e + 4 <= end; e += 4) {
        int s0 = __ldg(esrc + e + 0);
        int s1 = __ldg(esrc + e + 1);
        int s2 = __ldg(esrc + e + 2);
        int s3 = __ldg(esrc + e + 3);
        float4 v0 = __ldg((const float4*)(H + (size_t)s0 * C) + lc);
        float4 v1 = __ldg((const float4*)(H + (size_t)s1 * C) + lc);
        float4 v2 = __ldg((const float4*)(H + (size_t)s2 * C) + lc);
        float4 v3 = __ldg((const float4*)(H + (size_t)s3 * C) + lc);
        acc.x += v0.x + v1.x + v2.x + v3.x;
        acc.y += v0.y + v1.y + v2.y + v3.y;
        acc.z += v0.z + v1.z + v2.z + v3.z;
        acc.w += v0.w + v1.w + v2.w + v3.w;
    }
    for (; e < end; e++) {
        int s = __ldg(esrc + e);
        float4 v = __ldg((const float4*)(H + (size_t)s * C) + lc);
        acc.x += v.x; acc.y += v.y; acc.z += v.z; acc.w += v.w;
    }
    float nd = ndstAll[gidx * NNODES + row];
    float4 b = ((const float4*)bias)[lc];
    acc.x = fmaf(acc.x, nd, b.x);
    acc.y = fmaf(acc.y, nd, b.y);
    acc.z = fmaf(acc.z, nd, b.z);
    acc.w = fmaf(acc.w, nd, b.w);
    *((float4*)(out + (size_t)row * C) + lc) = acc;
}

// ---------------- launch ----------------
extern "C" void kernel_launch(void* const* d_in, const int* in_sizes, int n_in,
                              void* d_out, int out_size)
{
    float *XS, *H2, *nsrc, *ndst;
    int *cnt, *outcnt, *rowstart, *esrc;
    uint32_t *w1h, *w1l, *w2h, *w2l;
    cudaGetSymbolAddress((void**)&XS,       g_XS);
    cudaGetSymbolAddress((void**)&H2,       g_H2);
    cudaGetSymbolAddress((void**)&cnt,      g_cnt);
    cudaGetSymbolAddress((void**)&outcnt,   g_outcnt);
    cudaGetSymbolAddress((void**)&rowstart, g_rowstart);
    cudaGetSymbolAddress((void**)&esrc,     g_esrc);
    cudaGetSymbolAddress((void**)&nsrc,     g_nsrc);
    cudaGetSymbolAddress((void**)&ndst,     g_ndst);
    cudaGetSymbolAddress((void**)&w1h,      g_W1h);
    cudaGetSymbolAddress((void**)&w1l,      g_W1l);
    cudaGetSymbolAddress((void**)&w2h,      g_W2h);
    cudaGetSymbolAddress((void**)&w2l,      g_W2l);

    F3 feats = {{ (const float*)d_in[0], (const float*)d_in[3], (const float*)d_in[6] }};
    I3 srcs  = {{ (const int*)d_in[1],   (const int*)d_in[4],   (const int*)d_in[7] }};
    I3 dsts  = {{ (const int*)d_in[2],   (const int*)d_in[5],   (const int*)d_in[8] }};
    const float* W1 = (const float*)d_in[9];
    const float* b1 = (const float*)d_in[10];
    const float* W2 = (const float*)d_in[11];
    const float* b2 = (const float*)d_in[12];

    static const size_t SMEM_BYTES = SMEM_WORDS * sizeof(uint32_t);
    cudaFuncSetAttribute(fused_gemm, cudaFuncAttributeMaxDynamicSharedMemorySize,
                         (int)SMEM_BYTES);

    dim3 gE((NEDGES + 255) / 256, 3);
    dim3 gG((NNODES + 127) / 128, 3);
    dim3 gS1((NNODES * 32 + 255) / 256, 3);
    dim3 gS2((NNODES * 16 + 255) / 256, 3);

    zero_all <<<(3 * NNODES + 255) / 256, 256>>>(cnt, outcnt);
    hist_all <<<gE, 256>>>(srcs, dsts, cnt, outcnt);
    scan_all <<<3, 1024>>>(cnt, rowstart);
    norms_all<<<(3 * NNODES + 255) / 256, 256>>>(outcnt, rowstart, nsrc, ndst);
    fill_all <<<gE, 256>>>(srcs, dsts, rowstart, cnt, esrc);
    packW    <<<32, 256>>>(W1, W2, w1h, w1l, w2h, w2l);

    // XS = spmm(nsrc * feat)
    spmm_scaled<<<gS1, 256>>>(feats, rowstart, esrc, XS, nsrc);
    // H2 = relu((XS@W1)*ndst + b1) @ W2 * nsrc
    fused_gemm<<<gG, 256, SMEM_BYTES>>>(XS, w1h, w1l, w2h, w2l, b1, H2, nsrc, ndst);
    // out = gather(H2)*ndst + b2
    spmm_out<<<gS2, 256>>>(H2, rowstart, esrc, (float*)d_out, ndst, b2);
}